// round 2
// baseline (speedup 1.0000x reference)
#include <cuda_runtime.h>
#include <cstdint>

#define IN_CH 16
#define OUT_CH 64
#define HDIM 32
#define WDIM 32
#define NB 8
#define KHW 9
#define F (IN_CH * KHW)      // 144
#define OCG 8                // out channels per thread/block
#define ROWS 4               // output rows per block
#define TPB 128              // 4 rows * 32 cols

// add.rn.f32x2: packed fp32x2 add (Blackwell). Returns the two lanes unpacked.
__device__ __forceinline__ float2 padd2(unsigned long long a, unsigned long long b) {
    unsigned long long r;
    asm("add.rn.f32x2 %0, %1, %2;" : "=l"(r) : "l"(a), "l"(b));
    float2 out;
    asm("mov.b64 {%0, %1}, %2;" : "=f"(out.x), "=f"(out.y) : "l"(r));
    return out;
}

__global__ __launch_bounds__(TPB) void normdist_kernel(
    const float* __restrict__ x,      // (8,16,32,32)
    const float* __restrict__ weight, // (64,144)
    const float* __restrict__ bias,   // (64)
    float* __restrict__ out)          // (8,64,32,32)
{
    const int og   = blockIdx.x;          // 0..7 out-channel group (8 ch)
    const int rg   = blockIdx.y;          // 0..7 row group (4 rows)
    const int n    = blockIdx.z;          // 0..7 batch
    const int tid  = threadIdx.x;
    const int r    = tid >> 5;            // 0..3 row within tile (one warp per row)
    const int cpos = tid & 31;            // 0..31 col

    const int row0 = rg * ROWS;

    // x tile, DUPLICATED per element so a single LDS.64 yields the packed (p,p)
    // operand for add.rn.f32x2. rr in [0,6) -> global row row0-1+rr; cc in [0,34).
    __shared__ float2 xd[IN_CH][ROWS + 2][WDIM + 2];          // 26112 B
    // negated weights, transposed: wneg[f*8 + oo] = -weight[(og*8+oo)*144 + f]
    __shared__ __align__(16) float wneg[F * OCG];             // 4608 B

    // ---- fill negated transposed weights
    for (int idx = tid; idx < F * OCG; idx += TPB) {
        int oo = idx & (OCG - 1);
        int f  = idx >> 3;
        wneg[idx] = -weight[(og * OCG + oo) * F + f];
    }

    // ---- fill duplicated x tile with halo (zero padding)
    const float* xn = x + (size_t)n * IN_CH * HDIM * WDIM;
    const int tile_elems = IN_CH * (ROWS + 2) * (WDIM + 2);   // 16*6*34 = 3264
    for (int idx = tid; idx < tile_elems; idx += TPB) {
        int c   = idx / ((ROWS + 2) * (WDIM + 2));
        int rem = idx % ((ROWS + 2) * (WDIM + 2));
        int rr  = rem / (WDIM + 2);
        int cc  = rem % (WDIM + 2);
        int gr  = row0 - 1 + rr;
        int gc  = cc - 1;
        float v = 0.0f;
        if (gr >= 0 && gr < HDIM && gc >= 0 && gc < WDIM)
            v = xn[(c * HDIM + gr) * WDIM + gc];
        xd[c][rr][cc] = make_float2(v, v);
    }
    __syncthreads();

    float acc[OCG];
    #pragma unroll
    for (int o = 0; o < OCG; o++) acc[o] = 0.0f;   // |.| >= 0

    #pragma unroll 4
    for (int c = 0; c < IN_CH; c++) {
        // packed patch values (p,p): one conflict-free LDS.64 each
        unsigned long long pp[KHW];
        #pragma unroll
        for (int i = 0; i < 3; i++)
            #pragma unroll
            for (int j = 0; j < 3; j++)
                pp[i * 3 + j] = *reinterpret_cast<const unsigned long long*>(
                                    &xd[c][r + i][cpos + j]);

        #pragma unroll
        for (int j = 0; j < KHW; j++) {
            const int f = c * KHW + j;
            // 8 negated weights for this f: two LDS.128, each .x/.y an aligned reg pair
            const ulonglong2* wp = reinterpret_cast<const ulonglong2*>(&wneg[f * OCG]);
            ulonglong2 wa = wp[0];
            ulonglong2 wb = wp[1];

            float2 d0 = padd2(pp[j], wa.x);   // p - w[0], p - w[1]
            float2 d1 = padd2(pp[j], wa.y);
            float2 d2 = padd2(pp[j], wb.x);
            float2 d3 = padd2(pp[j], wb.y);

            acc[0] = fmaxf(acc[0], fabsf(d0.x));
            acc[1] = fmaxf(acc[1], fabsf(d0.y));
            acc[2] = fmaxf(acc[2], fabsf(d1.x));
            acc[3] = fmaxf(acc[3], fabsf(d1.y));
            acc[4] = fmaxf(acc[4], fabsf(d2.x));
            acc[5] = fmaxf(acc[5], fabsf(d2.y));
            acc[6] = fmaxf(acc[6], fabsf(d3.x));
            acc[7] = fmaxf(acc[7], fabsf(d3.y));
        }
    }

    // ---- write out: out[n][og*8+oo][row0+r][cpos]
    const int orow = row0 + r;
    float* outp = out + (((size_t)n * OUT_CH + og * OCG) * HDIM + orow) * WDIM + cpos;
    #pragma unroll
    for (int o = 0; o < OCG; o++) {
        outp[(size_t)o * HDIM * WDIM] = acc[o] + bias[og * OCG + o];
    }
}

extern "C" void kernel_launch(void* const* d_in, const int* in_sizes, int n_in,
                              void* d_out, int out_size) {
    const float* x      = (const float*)d_in[0];
    const float* weight = (const float*)d_in[1];
    const float* bias   = (const float*)d_in[2];
    float* out          = (float*)d_out;

    dim3 grid(OUT_CH / OCG, HDIM / ROWS, NB);   // (8, 8, 8) = 512 blocks
    normdist_kernel<<<grid, TPB>>>(x, weight, bias, out);
}

// round 3
// speedup vs baseline: 1.0405x; 1.0405x over previous
#include <cuda_runtime.h>

#define IN_CH 16
#define OUT_CH 64
#define HDIM 32
#define WDIM 32
#define NB 8
#define KHW 9
#define F (IN_CH * KHW)      // 144
#define OCG 8                // out channels per thread
#define ROWS 4               // output rows per block
#define CSPLIT 2             // input channels split across thread pairs
#define CPT (IN_CH / CSPLIT) // 8 input channels per thread
#define TPB (CSPLIT * ROWS * 32)  // 256

__global__ __launch_bounds__(TPB) void normdist_kernel(
    const float* __restrict__ x,      // (8,16,32,32)
    const float* __restrict__ weight, // (64,144)
    const float* __restrict__ bias,   // (64)
    float* __restrict__ out)          // (8,64,32,32)
{
    const int og    = blockIdx.x;          // 0..7 out-channel group (8 ch)
    const int rg    = blockIdx.y;          // 0..7 row group (4 rows)
    const int n     = blockIdx.z;          // 0..7 batch
    const int tid   = threadIdx.x;
    const int chalf = tid >> 7;            // 0/1: which half of input channels
    const int wtid  = tid & 127;
    const int r     = wtid >> 5;           // 0..3 row within tile
    const int cpos  = wtid & 31;           // 0..31 col

    const int row0 = rg * ROWS;

    // padded x tile: rr in [0,6) -> global row row0-1+rr, cc in [0,34)
    __shared__ float xs[IN_CH][ROWS + 2][WDIM + 2];           // 13056 B
    // transposed weights: wT[f][oo] = weight[(og*8+oo)*144 + f]
    __shared__ __align__(16) float wT[F][OCG];                // 4608 B
    // partial-max exchange buffer (pad 9 -> conflict-free)
    __shared__ float ps[ROWS][32][OCG + 1];                   // 4608 B

    // ---- load transposed weight chunk
    for (int idx = tid; idx < F * OCG; idx += TPB) {
        int oo = idx & (OCG - 1);
        int f  = idx >> 3;
        wT[f][oo] = weight[(og * OCG + oo) * F + f];
    }

    // ---- load x tile with halo (zero padding)
    const float* xn = x + (size_t)n * IN_CH * HDIM * WDIM;
    const int tile_elems = IN_CH * (ROWS + 2) * (WDIM + 2);   // 3264
    for (int idx = tid; idx < tile_elems; idx += TPB) {
        int c   = idx / ((ROWS + 2) * (WDIM + 2));
        int rem = idx % ((ROWS + 2) * (WDIM + 2));
        int rr  = rem / (WDIM + 2);
        int cc  = rem % (WDIM + 2);
        int gr  = row0 - 1 + rr;
        int gc  = cc - 1;
        float v = 0.0f;
        if (gr >= 0 && gr < HDIM && gc >= 0 && gc < WDIM)
            v = xn[(c * HDIM + gr) * WDIM + gc];
        xs[c][rr][cc] = v;
    }
    __syncthreads();

    float acc[OCG];
    #pragma unroll
    for (int o = 0; o < OCG; o++) acc[o] = 0.0f;   // |.| >= 0

    const int c0 = chalf * CPT;
    #pragma unroll 2
    for (int ci = 0; ci < CPT; ci++) {
        const int c = c0 + ci;
        // 3x3 patch into registers
        float p[KHW];
        #pragma unroll
        for (int i = 0; i < 3; i++)
            #pragma unroll
            for (int j = 0; j < 3; j++)
                p[i * 3 + j] = xs[c][r + i][cpos + j];

        #pragma unroll
        for (int j = 0; j < KHW; j++) {
            const int f = c * KHW + j;
            const float4* w4 = reinterpret_cast<const float4*>(&wT[f][0]);
            float4 wa = w4[0], wb = w4[1];   // 2x LDS.128 broadcast
            const float pj = p[j];
            acc[0] = fmaxf(acc[0], fabsf(pj - wa.x));
            acc[1] = fmaxf(acc[1], fabsf(pj - wa.y));
            acc[2] = fmaxf(acc[2], fabsf(pj - wa.z));
            acc[3] = fmaxf(acc[3], fabsf(pj - wa.w));
            acc[4] = fmaxf(acc[4], fabsf(pj - wb.x));
            acc[5] = fmaxf(acc[5], fabsf(pj - wb.y));
            acc[6] = fmaxf(acc[6], fabsf(pj - wb.z));
            acc[7] = fmaxf(acc[7], fabsf(pj - wb.w));
        }
    }

    // ---- combine the two c-halves: half 1 writes partials, half 0 reduces
    if (chalf == 1) {
        #pragma unroll
        for (int o = 0; o < OCG; o++) ps[r][cpos][o] = acc[o];
    }
    __syncthreads();

    if (chalf == 0) {
        const int orow = row0 + r;
        float* outp = out + (((size_t)n * OUT_CH + og * OCG) * HDIM + orow) * WDIM + cpos;
        #pragma unroll
        for (int o = 0; o < OCG; o++) {
            float v = fmaxf(acc[o], ps[r][cpos][o]) + bias[og * OCG + o];
            outp[(size_t)o * HDIM * WDIM] = v;
        }
    }
}

extern "C" void kernel_launch(void* const* d_in, const int* in_sizes, int n_in,
                              void* d_out, int out_size) {
    const float* x      = (const float*)d_in[0];
    const float* weight = (const float*)d_in[1];
    const float* bias   = (const float*)d_in[2];
    float* out          = (float*)d_out;

    dim3 grid(OUT_CH / OCG, HDIM / ROWS, NB);   // (8, 8, 8) = 512 blocks
    normdist_kernel<<<grid, TPB>>>(x, weight, bias, out);
}